// round 3
// baseline (speedup 1.0000x reference)
#include <cuda_runtime.h>
#include <cuda_bf16.h>

// Problem constants
#define BB 128
#define FHH 26
#define FWW 26
#define TT 50
#define AA 5
#define NCLS 20
#define KK (FHH*FWW)          // 676
#define KA (KK*AA)            // 3380
#define CH (5+NCLS)           // 25
#define OBJ_SCALE 5.0f

#define SPARTS 5              // one streaming part per anchor type
#define NPARTS (SPARTS + 1)   // + assignment part
#define THR 256
#define NA 3                  // k's per thread (256*3 = 768 >= 676)
#define SQ7 2.6457513110645906f

__constant__ float c_aw[AA] = {1.3221f, 3.19275f, 5.05587f, 9.47112f, 11.2364f};
__constant__ float c_ah[AA] = {1.73145f, 4.00944f, 8.09892f, 4.84053f, 10.0071f};

// Scratch
__device__ float4 g_part[BB][NPARTS];  // streaming: (sumAll, sumFlag, 0, posAny)
                                       // part 5:   (corrA,  corrB,  asgLoss, 0)
__device__ unsigned g_done = 0;

__device__ __forceinline__ float sigmoidf_(float x) {
    return 1.0f / (1.0f + __expf(-x));
}

// Shared decode: coordinates pre-scaled by sqrt(7) so 7*inter == ix*iy.
// pa3 = 3 * unscaled area (threshold); pa7 = scaled area = 7*pa (for miou den).
__device__ __forceinline__ void decode_core(
    const float* __restrict__ p, int a, int k,
    float& px1, float& py1, float& px2, float& py2,
    float& pa3, float& conf, float& sx, float& sy,
    float& ew, float& eh, float& pa7)
{
    int yy = k / FWW, xx = k - yy * FWW;
    float tx = p[0], ty = p[KK], tw = p[2*KK], th = p[3*KK], tc = p[4*KK];
    sx = sigmoidf_(tx); sy = sigmoidf_(ty);
    ew = __expf(tw);    eh = __expf(th);
    conf = sigmoidf_(tc);
    float pw = c_aw[a] * ew, ph = c_ah[a] * eh;
    float pa = pw * ph;
    pa3 = 3.0f * pa;
    float pcx = (float)xx + sx, pcy = (float)yy + sy;
    float pwS = SQ7 * pw, phS = SQ7 * ph;
    px1 = fmaf(SQ7, pcx, -0.5f * pwS);
    px2 = fmaf(SQ7, pcx,  0.5f * pwS);
    py1 = fmaf(SQ7, pcy, -0.5f * phS);
    py2 = fmaf(SQ7, pcy,  0.5f * phS);
    pa7 = pwS * phS;
}

// ---------------------------------------------------------------------------
// Single fused kernel: grid (B, 6).
//   part < 5 : streaming over k for anchor type a = part
//   part == 5: assignment + assigned-anchor losses + corrections
// The very last block to finish performs the global combine and writes out.
// ---------------------------------------------------------------------------
__global__ __launch_bounds__(THR)
void mainKernel(const float* __restrict__ outputs,
                const float* __restrict__ targets,
                float* __restrict__ out) {
    const int b    = blockIdx.x;
    const int part = blockIdx.y;
    const int tid  = threadIdx.x;

    __shared__ float4 s_gt[TT];    // sqrt7-scaled xxyy (sanitized if invalid)
    __shared__ float  s_mga3[TT];  // -3 * unscaled gt area
    __shared__ float  s_ga7[TT];   // 7 * unscaled gt area
    // part-5 only
    __shared__ int    s_slot[TT];
    __shared__ int    s_valid[TT];
    __shared__ float4 s_tb[TT];
    __shared__ int    s_cls[TT];

    // ---- prolog ----
    if (tid < TT) {
        const float* g = targets + ((size_t)b * TT + tid) * 5;
        float x1 = g[0], y1 = g[1], x2 = g[2], y2 = g[3], cl = g[4];
        bool valid = (x1 + y1 + x2 + y2) > 0.0f;

        float gx1 = x1 * FWW, gy1 = y1 * FHH, gx2 = x2 * FWW, gy2 = y2 * FHH;
        float gw = gx2 - gx1, gh = gy2 - gy1;
        float ga = gw * gh;

        if (valid) {
            s_gt[tid] = make_float4(SQ7*gx1, SQ7*gy1, SQ7*gx2, SQ7*gy2);
            s_mga3[tid] = -3.0f * ga;
            s_ga7[tid]  = 7.0f * ga;
        } else {
            s_gt[tid] = make_float4(1e8f, 1e8f, 1e8f, 1e8f);
            s_mga3[tid] = 0.0f;
            s_ga7[tid]  = 0.0f;
        }

        if (part == SPARTS) {
            float gcx = 0.5f * (gx1 + gx2), gcy = 0.5f * (gy1 + gy2);
            int cx = min(max((int)floorf(gcx), 0), FWW - 1);
            int cy = min(max((int)floorf(gcy), 0), FHH - 1);
            int cell = cy * FWW + cx;

            float acx = (float)cx + 0.5f, acy = (float)cy + 0.5f;
            float best = -1e30f;
            int aidx = 0;
            #pragma unroll
            for (int a = 0; a < AA; a++) {
                float aw = c_aw[a], ah = c_ah[a];
                float ax1 = acx - 0.5f*aw, ax2 = acx + 0.5f*aw;
                float ay1 = acy - 0.5f*ah, ay2 = acy + 0.5f*ah;
                float xi1 = fmaxf(ax1, gx1), yi1 = fmaxf(ay1, gy1);
                float xi2 = fminf(ax2, gx2), yi2 = fminf(ay2, gy2);
                float inter = fmaxf(xi2 - xi1, 0.0f) * fmaxf(yi2 - yi1, 0.0f);
                float iou = inter / (aw * ah + ga - inter);
                if (iou > best) { best = iou; aidx = a; }
            }
            s_tb[tid]   = make_float4(gcx - (float)cx, gcy - (float)cy,
                                      gw / c_aw[aidx], gh / c_ah[aidx]);
            s_cls[tid]  = (int)cl;
            s_slot[tid] = cell * AA + aidx;
            s_valid[tid] = valid ? 1 : 0;
        }
    }
    __syncthreads();

    const float* ob = outputs + (size_t)b * CH * KA;

    float r0 = 0.0f, r1 = 0.0f, r2 = 0.0f, r3 = 0.0f;

    if (part < SPARTS) {
        // -------------------- streaming: anchor type a = part --------------
        const int a = part;
        const float* pbase = ob + (size_t)(a * CH) * KK;

        float px1[NA], py1[NA], px2[NA], py2[NA], pa3[NA], c2[NA];
        bool v[NA];
        #pragma unroll
        for (int j = 0; j < NA; j++) {
            int k = tid + j * THR;
            v[j] = k < KK;
            int kc = v[j] ? k : (KK - 1);
            float conf, sx, sy, ew, eh, pa7;
            decode_core(pbase + kc, a, kc,
                        px1[j], py1[j], px2[j], py2[j], pa3[j],
                        conf, sx, sy, ew, eh, pa7);
            c2[j] = conf * conf;
        }

        float acc[NA];
        #pragma unroll
        for (int j = 0; j < NA; j++) acc[j] = 0.0f;

        #pragma unroll 5
        for (int t = 0; t < TT; t++) {
            float4 g = s_gt[t];
            float mg = s_mga3[t];
            #pragma unroll
            for (int j = 0; j < NA; j++) {
                float dx = fminf(px2[j], g.z) - fmaxf(px1[j], g.x);
                float dy = fminf(py2[j], g.w) - fmaxf(py1[j], g.y);
                float ix = fmaxf(dx, 0.0f);
                float iy = fmaxf(dy, 0.0f);
                acc[j] = fmaxf(acc[j], fmaf(ix, iy, mg));
            }
        }

        float posAny = 0.0f;
        #pragma unroll
        for (int j = 0; j < NA; j++) {
            if (v[j]) {
                r0 += c2[j];                          // sumAll
                if (acc[j] >= pa3[j]) r1 += c2[j];    // iou >= 0.75
                if (acc[j] >  pa3[j]) posAny = 1.0f;  // iou >  0.75
            }
        }
        r3 = posAny;
    } else {
        // -------------------- assignment part -------------------------------
        __shared__ int s_fslot[TT];
        if (tid < TT) {
            int slot = s_slot[tid];
            bool fin = (s_valid[tid] != 0);
            if (fin) {
                for (int t2 = tid + 1; t2 < TT; t2++)
                    if (s_valid[t2] && s_slot[t2] == slot) { fin = false; break; }
            }
            s_fslot[tid] = fin ? slot : -1;
        }
        __syncthreads();

        if (tid < TT && s_fslot[tid] >= 0) {
            int slot = s_fslot[tid];
            int k = slot / AA, a = slot - k * AA;
            const float* p = ob + (size_t)(a * CH) * KK + k;

            float px1, py1, px2, py2, pa3, conf, sx, sy, ew, eh, pa7;
            decode_core(p, a, k, px1, py1, px2, py2, pa3,
                        conf, sx, sy, ew, eh, pa7);

            // exact max-IoU (division-free) + identical algebraic flag
            float bi = 0.0f, bd = 1.0f, acc = 0.0f;
            for (int t = 0; t < TT; t++) {
                float4 g = s_gt[t];
                float dx = fminf(px2, g.z) - fmaxf(px1, g.x);
                float dy = fminf(py2, g.w) - fmaxf(py1, g.y);
                float ix = fmaxf(dx, 0.0f);
                float iy = fmaxf(dy, 0.0f);
                float inter = ix * iy;                       // scaled (=7*inter)
                float den = pa7 + s_ga7[t] - inter;          // scaled
                bool win = (inter * bd > bi * den);
                bi = win ? inter : bi;
                bd = win ? den : bd;
                acc = fmaxf(acc, fmaf(ix, iy, s_mga3[t]));   // same as streaming
            }
            float miou = bi / bd;  // scale cancels

            float4 tb = s_tb[tid];
            float d0 = sx - tb.x, d1 = sy - tb.y;
            float d2 = ew - tb.z, d3 = eh - tb.w;
            float asg = 0.5f * (d0*d0 + d1*d1 + d2*d2 + d3*d3);
            float di = OBJ_SCALE * conf - OBJ_SCALE * miou;
            asg += 0.5f * di * di;
            // class CE
            float lmax = -1e30f;
            #pragma unroll
            for (int c = 0; c < NCLS; c++) lmax = fmaxf(lmax, p[(5 + c) * KK]);
            float se = 0.0f;
            #pragma unroll
            for (int c = 0; c < NCLS; c++) se += __expf(p[(5 + c) * KK] - lmax);
            asg += (lmax + __logf(se)) - p[(5 + s_cls[tid]) * KK];

            r2 = asg;
            float c2 = conf * conf;
            r0 = -c2;
            if (acc >= pa3) r1 = -c2;
        }
    }

    // ---- block reduction (deterministic within block) ----
    #pragma unroll
    for (int o = 16; o > 0; o >>= 1) {
        r0 += __shfl_down_sync(0xffffffffu, r0, o);
        r1 += __shfl_down_sync(0xffffffffu, r1, o);
        r2 += __shfl_down_sync(0xffffffffu, r2, o);
        r3 += __shfl_down_sync(0xffffffffu, r3, o);
    }
    __shared__ float rA[THR/32], rBs[THR/32], rG[THR/32], rP[THR/32];
    int w = tid >> 5, l = tid & 31;
    if (l == 0) { rA[w] = r0; rBs[w] = r1; rG[w] = r2; rP[w] = r3; }
    __syncthreads();

    __shared__ int s_last;
    if (tid == 0) {
        float a0 = 0, b0 = 0, g0 = 0, p0 = 0;
        #pragma unroll
        for (int i = 0; i < THR/32; i++) {
            a0 += rA[i]; b0 += rBs[i]; g0 += rG[i]; p0 += rP[i];
        }
        g_part[b][part] = make_float4(a0, b0, g0, p0);
        __threadfence();
        unsigned done = atomicAdd(&g_done, 1u);
        s_last = (done == (unsigned)(BB * NPARTS - 1)) ? 1 : 0;
    }
    __syncthreads();

    // ---- last block: global combine (deterministic order) ----
    if (s_last) {
        __shared__ float red[BB];
        if (tid < BB) {
            float sA = 0, sB = 0, sG = 0, sP = 0;
            #pragma unroll
            for (int p = 0; p < NPARTS; p++) {
                float4 v = g_part[tid][p];
                sA += v.x; sB += v.y; sG += v.z; sP += v.w;
            }
            bool pos = sP > 0.0f;
            red[tid] = 0.5f * (sA - (pos ? sB : 0.0f)) + sG;
        }
        __syncthreads();
        #pragma unroll
        for (int s = BB / 2; s > 0; s >>= 1) {
            if (tid < s) red[tid] += red[tid + s];
            __syncthreads();
        }
        if (tid == 0) {
            out[0] = red[0] / (float)BB;
            g_done = 0;  // reset for next graph replay
        }
    }
}

// ---------------------------------------------------------------------------
extern "C" void kernel_launch(void* const* d_in, const int* in_sizes, int n_in,
                              void* d_out, int out_size) {
    const float* outputs = (const float*)d_in[0];
    const float* targets = (const float*)d_in[1];
    if (n_in >= 2 && in_sizes[0] < in_sizes[1]) {
        outputs = (const float*)d_in[1];
        targets = (const float*)d_in[0];
    }
    float* out = (float*)d_out;

    dim3 grid(BB, NPARTS);
    mainKernel<<<grid, THR>>>(outputs, targets, out);
}

// round 5
// speedup vs baseline: 1.1000x; 1.1000x over previous
#include <cuda_runtime.h>
#include <cuda_bf16.h>

// Problem constants
#define BB 128
#define FHH 26
#define FWW 26
#define TT 50
#define AA 5
#define NCLS 20
#define KK (FHH*FWW)          // 676
#define KA (KK*AA)            // 3380
#define CH (5+NCLS)           // 25
#define OBJ_SCALE 5.0f

#define TLS 13                // tile side (13x13 cells)
#define TILES 4               // 2x2 tiles
#define CPT (TLS*TLS)         // 169 cells per tile
#define SPARTS (AA*TILES)     // 20 streaming parts
#define NPARTS (SPARTS + 1)   // + assignment part
#define THR 96
#define NA 2                  // cells per thread (96*2 = 192 >= 169)
#define NW (THR/32)           // 3 warps
#define SQ7 2.6457513110645906f

__constant__ float c_aw[AA] = {1.3221f, 3.19275f, 5.05587f, 9.47112f, 11.2364f};
__constant__ float c_ah[AA] = {1.73145f, 4.00944f, 8.09892f, 4.84053f, 10.0071f};

// Scratch
__device__ float4 g_part[BB][NPARTS];
__device__ unsigned g_done = 0;

__device__ __forceinline__ float sigmoidf_(float x) {
    return 1.0f / (1.0f + __expf(-x));
}

// Decode (sqrt7-scaled corners; nx1/ny1 = NEGATED lower corners).
__device__ __forceinline__ void decode_core(
    const float* __restrict__ p, int a, int xx, int yy,
    float& nx1, float& ny1, float& px2, float& py2,
    float& pa3, float& conf, float& sx, float& sy,
    float& ew, float& eh, float& pa7)
{
    float tx = p[0], ty = p[KK], tw = p[2*KK], th = p[3*KK], tc = p[4*KK];
    sx = sigmoidf_(tx); sy = sigmoidf_(ty);
    ew = __expf(tw);    eh = __expf(th);
    conf = sigmoidf_(tc);
    float pw = c_aw[a] * ew, ph = c_ah[a] * eh;
    float pa = pw * ph;
    pa3 = 3.0f * pa;
    float pcx = (float)xx + sx, pcy = (float)yy + sy;
    float pwS = SQ7 * pw, phS = SQ7 * ph;
    float px1 = fmaf(SQ7, pcx, -0.5f * pwS);
    px2       = fmaf(SQ7, pcx,  0.5f * pwS);
    float py1 = fmaf(SQ7, pcy, -0.5f * phS);
    py2       = fmaf(SQ7, pcy,  0.5f * phS);
    nx1 = -px1; ny1 = -py1;
    pa7 = pwS * phS;
}

// ---------------------------------------------------------------------------
// grid (B, 21): part = a*4 + tile for part < 20; part 20 = assignment.
// Last block of all performs the global combine.
// ---------------------------------------------------------------------------
__global__ __launch_bounds__(THR)
void mainKernel(const float* __restrict__ outputs,
                const float* __restrict__ targets,
                float* __restrict__ out) {
    const int b    = blockIdx.x;
    const int part = blockIdx.y;
    const int tid  = threadIdx.x;

    __shared__ float4 s_gt[TT];    // scaled (X1,Y1,X2,Y2), sanitized
    __shared__ float  s_mga3[TT];  // -3 * unscaled gt area
    __shared__ float  s_ga7[TT];   // 7 * unscaled gt area (assignment)
    // compacted gt list (streaming)
    __shared__ float4 s_cgt[TT];   // (X2, Y2, -X1, -Y1)
    __shared__ float  s_cmg[TT];
    __shared__ int    s_cnt;
    __shared__ float4 s_bbox;      // (xlo, ylo, xhi, yhi)
    __shared__ float  s_wlo[NW][2], s_whi[NW][2];
    // assignment-only
    __shared__ int    s_slot[TT];
    __shared__ int    s_valid[TT];
    __shared__ float4 s_tb[TT];
    __shared__ int    s_cls[TT];

    if (tid == 0) s_cnt = 0;

    // ---- gt decode ----
    if (tid < TT) {
        const float* g = targets + ((size_t)b * TT + tid) * 5;
        float x1 = g[0], y1 = g[1], x2 = g[2], y2 = g[3], cl = g[4];
        bool valid = (x1 + y1 + x2 + y2) > 0.0f;

        float gx1 = x1 * FWW, gy1 = y1 * FHH, gx2 = x2 * FWW, gy2 = y2 * FHH;
        float gw = gx2 - gx1, gh = gy2 - gy1;
        float ga = gw * gh;

        if (valid) {
            s_gt[tid] = make_float4(SQ7*gx1, SQ7*gy1, SQ7*gx2, SQ7*gy2);
            s_mga3[tid] = -3.0f * ga;
            s_ga7[tid]  = 7.0f * ga;
        } else {
            s_gt[tid] = make_float4(1e8f, 1e8f, 1e8f, 1e8f);
            s_mga3[tid] = 0.0f;
            s_ga7[tid]  = 0.0f;
        }

        if (part == SPARTS) {
            float gcx = 0.5f * (gx1 + gx2), gcy = 0.5f * (gy1 + gy2);
            int cx = min(max((int)floorf(gcx), 0), FWW - 1);
            int cy = min(max((int)floorf(gcy), 0), FHH - 1);
            int cell = cy * FWW + cx;

            float acx = (float)cx + 0.5f, acy = (float)cy + 0.5f;
            float best = -1e30f;
            int aidx = 0;
            #pragma unroll
            for (int a = 0; a < AA; a++) {
                float aw = c_aw[a], ah = c_ah[a];
                float ax1 = acx - 0.5f*aw, ax2 = acx + 0.5f*aw;
                float ay1 = acy - 0.5f*ah, ay2 = acy + 0.5f*ah;
                float xi1 = fmaxf(ax1, gx1), yi1 = fmaxf(ay1, gy1);
                float xi2 = fminf(ax2, gx2), yi2 = fminf(ay2, gy2);
                float inter = fmaxf(xi2 - xi1, 0.0f) * fmaxf(yi2 - yi1, 0.0f);
                float iou = inter / (aw * ah + ga - inter);
                if (iou > best) { best = iou; aidx = a; }
            }
            s_tb[tid]   = make_float4(gcx - (float)cx, gcy - (float)cy,
                                      gw / c_aw[aidx], gh / c_ah[aidx]);
            s_cls[tid]  = (int)cl;
            s_slot[tid] = cell * AA + aidx;
            s_valid[tid] = valid ? 1 : 0;
        }
    }

    const float* ob = outputs + (size_t)b * CH * KA;

    float r0 = 0.0f, r1 = 0.0f, r2 = 0.0f, r3 = 0.0f;

    if (part < SPARTS) {
        // -------------------- streaming: anchor a, tile (tx,ty) -------------
        const int a    = part >> 2;
        const int tile = part & 3;
        const int tx   = tile & 1;
        const int ty   = tile >> 1;
        const float* pbase = ob + (size_t)(a * CH) * KK;

        float nx1[NA], ny1[NA], px2[NA], py2[NA], pa3[NA], c2[NA];
        bool v[NA];
        #pragma unroll
        for (int j = 0; j < NA; j++) {
            int slot = tid + j * THR;
            v[j] = slot < CPT;
            int lc = v[j] ? slot : (CPT - 1);
            int ly = lc / TLS, lx = lc - ly * TLS;
            int xx = tx * TLS + lx, yy = ty * TLS + ly;
            int k = yy * FWW + xx;
            float conf, sx, sy, ew, eh, pa7;
            decode_core(pbase + k, a, xx, yy, nx1[j], ny1[j], px2[j], py2[j],
                        pa3[j], conf, sx, sy, ew, eh, pa7);
            c2[j] = conf * conf;
        }

        // block bbox over all anchors (padded ones only enlarge -> safe)
        float bxlo = fminf(-nx1[0], -nx1[1]);
        float bylo = fminf(-ny1[0], -ny1[1]);
        float bxhi = fmaxf(px2[0], px2[1]);
        float byhi = fmaxf(py2[0], py2[1]);
        #pragma unroll
        for (int o = 16; o > 0; o >>= 1) {
            bxlo = fminf(bxlo, __shfl_xor_sync(0xffffffffu, bxlo, o));
            bylo = fminf(bylo, __shfl_xor_sync(0xffffffffu, bylo, o));
            bxhi = fmaxf(bxhi, __shfl_xor_sync(0xffffffffu, bxhi, o));
            byhi = fmaxf(byhi, __shfl_xor_sync(0xffffffffu, byhi, o));
        }
        int w = tid >> 5;
        if ((tid & 31) == 0) {
            s_wlo[w][0] = bxlo; s_wlo[w][1] = bylo;
            s_whi[w][0] = bxhi; s_whi[w][1] = byhi;
        }
        __syncthreads();
        if (tid == 0) {
            float xl = s_wlo[0][0], yl = s_wlo[0][1];
            float xh = s_whi[0][0], yh = s_whi[0][1];
            #pragma unroll
            for (int i = 1; i < NW; i++) {
                xl = fminf(xl, s_wlo[i][0]); yl = fminf(yl, s_wlo[i][1]);
                xh = fmaxf(xh, s_whi[i][0]); yh = fmaxf(yh, s_whi[i][1]);
            }
            s_bbox = make_float4(xl, yl, xh, yh);
        }
        __syncthreads();

        // compact gts overlapping the block bbox (order irrelevant: exact)
        if (tid < TT) {
            float4 g = s_gt[tid];
            float4 bbx = s_bbox;
            if (g.x < bbx.z && g.z > bbx.x && g.y < bbx.w && g.w > bbx.y) {
                int i = atomicAdd(&s_cnt, 1);
                s_cgt[i] = make_float4(g.z, g.w, -g.x, -g.y);
                s_cmg[i] = s_mga3[tid];
            }
        }
        __syncthreads();

        const int cnt = s_cnt;
        float acc[NA];
        #pragma unroll
        for (int j = 0; j < NA; j++) acc[j] = 0.0f;

        for (int i = 0; i < cnt; i++) {
            float4 c = s_cgt[i];
            float mg = s_cmg[i];
            #pragma unroll
            for (int j = 0; j < NA; j++) {
                float dx = fminf(px2[j], c.x) + fminf(nx1[j], c.z);
                float dy = fminf(py2[j], c.y) + fminf(ny1[j], c.w);
                float ix = fmaxf(dx, 0.0f);
                float iy = fmaxf(dy, 0.0f);
                acc[j] = fmaxf(acc[j], fmaf(ix, iy, mg));
            }
        }

        float posAny = 0.0f;
        #pragma unroll
        for (int j = 0; j < NA; j++) {
            if (v[j]) {
                r0 += c2[j];
                if (acc[j] >= pa3[j]) r1 += c2[j];
                if (acc[j] >  pa3[j]) posAny = 1.0f;
            }
        }
        r3 = posAny;
    } else {
        // -------------------- assignment part -------------------------------
        __syncthreads();
        __shared__ int s_fslot[TT];
        if (tid < TT) {
            int slot = s_slot[tid];
            bool fin = (s_valid[tid] != 0);
            if (fin) {
                for (int t2 = tid + 1; t2 < TT; t2++)
                    if (s_valid[t2] && s_slot[t2] == slot) { fin = false; break; }
            }
            s_fslot[tid] = fin ? slot : -1;
        }
        __syncthreads();

        if (tid < TT && s_fslot[tid] >= 0) {
            int slot = s_fslot[tid];
            int k = slot / AA, a = slot - k * AA;
            int yy = k / FWW, xx = k - yy * FWW;
            const float* p = ob + (size_t)(a * CH) * KK + k;

            float nx1, ny1, px2, py2, pa3, conf, sx, sy, ew, eh, pa7;
            decode_core(p, a, xx, yy, nx1, ny1, px2, py2, pa3,
                        conf, sx, sy, ew, eh, pa7);

            // exact max-IoU over ALL gts + SAME algebraic flag expression
            float bi = 0.0f, bd = 1.0f, acc = 0.0f;
            for (int t = 0; t < TT; t++) {
                float4 g = s_gt[t];
                float dx = fminf(px2, g.z) + fminf(nx1, -g.x);
                float dy = fminf(py2, g.w) + fminf(ny1, -g.y);
                float ix = fmaxf(dx, 0.0f);
                float iy = fmaxf(dy, 0.0f);
                float inter = ix * iy;                 // scaled (=7*inter)
                float den = pa7 + s_ga7[t] - inter;
                bool win = (inter * bd > bi * den);
                bi = win ? inter : bi;
                bd = win ? den : bd;
                acc = fmaxf(acc, fmaf(ix, iy, s_mga3[t]));
            }
            float miou = bi / bd;

            float4 tb = s_tb[tid];
            float d0 = sx - tb.x, d1 = sy - tb.y;
            float d2 = ew - tb.z, d3 = eh - tb.w;
            float asg = 0.5f * (d0*d0 + d1*d1 + d2*d2 + d3*d3);
            float di = OBJ_SCALE * conf - OBJ_SCALE * miou;
            asg += 0.5f * di * di;
            float lmax = -1e30f;
            #pragma unroll
            for (int c = 0; c < NCLS; c++) lmax = fmaxf(lmax, p[(5 + c) * KK]);
            float se = 0.0f;
            #pragma unroll
            for (int c = 0; c < NCLS; c++) se += __expf(p[(5 + c) * KK] - lmax);
            asg += (lmax + __logf(se)) - p[(5 + s_cls[tid]) * KK];

            r2 = asg;
            float cc = conf * conf;
            r0 = -cc;
            if (acc >= pa3) r1 = -cc;
        }
    }

    // ---- block reduction ----
    #pragma unroll
    for (int o = 16; o > 0; o >>= 1) {
        r0 += __shfl_down_sync(0xffffffffu, r0, o);
        r1 += __shfl_down_sync(0xffffffffu, r1, o);
        r2 += __shfl_down_sync(0xffffffffu, r2, o);
        r3 += __shfl_down_sync(0xffffffffu, r3, o);
    }
    __shared__ float rA[NW], rBs[NW], rG[NW], rP[NW];
    int w2 = tid >> 5, l2 = tid & 31;
    if (l2 == 0) { rA[w2] = r0; rBs[w2] = r1; rG[w2] = r2; rP[w2] = r3; }
    __syncthreads();

    __shared__ int s_last;
    if (tid == 0) {
        float a0 = 0, b0 = 0, g0 = 0, p0 = 0;
        #pragma unroll
        for (int i = 0; i < NW; i++) {
            a0 += rA[i]; b0 += rBs[i]; g0 += rG[i]; p0 += rP[i];
        }
        g_part[b][part] = make_float4(a0, b0, g0, p0);
        __threadfence();
        unsigned done = atomicAdd(&g_done, 1u);
        s_last = (done == (unsigned)(BB * NPARTS - 1)) ? 1 : 0;
    }
    __syncthreads();

    // ---- last block: global combine (deterministic order) ----
    if (s_last) {
        __shared__ float red[64];
        if (tid < 64) {
            float accl = 0.0f;
            for (int bb = tid; bb < BB; bb += 64) {
                float sA = 0, sB = 0, sG = 0, sP = 0;
                #pragma unroll
                for (int p = 0; p < NPARTS; p++) {
                    float4 vv = g_part[bb][p];
                    sA += vv.x; sB += vv.y; sG += vv.z; sP += vv.w;
                }
                bool pos = sP > 0.0f;
                accl += 0.5f * (sA - (pos ? sB : 0.0f)) + sG;
            }
            red[tid] = accl;
        }
        __syncthreads();
        #pragma unroll
        for (int s = 32; s > 0; s >>= 1) {
            if (tid < s) red[tid] += red[tid + s];
            __syncthreads();
        }
        if (tid == 0) {
            out[0] = red[0] / (float)BB;
            g_done = 0;  // reset for next graph replay
        }
    }
}

// ---------------------------------------------------------------------------
extern "C" void kernel_launch(void* const* d_in, const int* in_sizes, int n_in,
                              void* d_out, int out_size) {
    const float* outputs = (const float*)d_in[0];
    const float* targets = (const float*)d_in[1];
    if (n_in >= 2 && in_sizes[0] < in_sizes[1]) {
        outputs = (const float*)d_in[1];
        targets = (const float*)d_in[0];
    }
    float* out = (float*)d_out;

    dim3 grid(BB, NPARTS);
    mainKernel<<<grid, THR>>>(outputs, targets, out);
}

// round 6
// speedup vs baseline: 1.2073x; 1.0976x over previous
#include <cuda_runtime.h>
#include <cuda_bf16.h>

// Problem constants
#define BB 128
#define FHH 26
#define FWW 26
#define TT 50
#define AA 5
#define NCLS 20
#define KK (FHH*FWW)          // 676
#define KA (KK*AA)            // 3380
#define CH (5+NCLS)           // 25
#define OBJ_SCALE 5.0f

#define TILES 2               // split grid into 2 y-halves (13 rows each)
#define CPT (KK/TILES)        // 338 cells per tile (contiguous k range)
#define SPARTS (AA*TILES)     // 10 streaming parts
#define NPARTS (SPARTS + 1)   // + assignment part
#define THR 96
#define NA 4                  // cells per thread (96*4 = 384 >= 338)
#define NW (THR/32)           // 3 warps
#define SQ7 2.6457513110645906f

__constant__ float c_aw[AA] = {1.3221f, 3.19275f, 5.05587f, 9.47112f, 11.2364f};
__constant__ float c_ah[AA] = {1.73145f, 4.00944f, 8.09892f, 4.84053f, 10.0071f};

// Scratch
__device__ float4 g_part[BB][NPARTS];
__device__ unsigned g_done = 0;

__device__ __forceinline__ float sigmoidf_(float x) {
    return 1.0f / (1.0f + __expf(-x));
}

// Decode (sqrt7-scaled corners; nx1/ny1 = NEGATED lower corners).
__device__ __forceinline__ void decode_core(
    const float* __restrict__ p, int a, int xx, int yy,
    float& nx1, float& ny1, float& px2, float& py2,
    float& pa3, float& conf, float& sx, float& sy,
    float& ew, float& eh, float& pa7)
{
    float tx = p[0], ty = p[KK], tw = p[2*KK], th = p[3*KK], tc = p[4*KK];
    sx = sigmoidf_(tx); sy = sigmoidf_(ty);
    ew = __expf(tw);    eh = __expf(th);
    conf = sigmoidf_(tc);
    float pw = c_aw[a] * ew, ph = c_ah[a] * eh;
    float pa = pw * ph;
    pa3 = 3.0f * pa;
    float pcx = (float)xx + sx, pcy = (float)yy + sy;
    float pwS = SQ7 * pw, phS = SQ7 * ph;
    float px1 = fmaf(SQ7, pcx, -0.5f * pwS);
    px2       = fmaf(SQ7, pcx,  0.5f * pwS);
    float py1 = fmaf(SQ7, pcy, -0.5f * phS);
    py2       = fmaf(SQ7, pcy,  0.5f * phS);
    nx1 = -px1; ny1 = -py1;
    pa7 = pwS * phS;
}

// ---------------------------------------------------------------------------
// grid (B, 11): part = a*2 + tile for part < 10; part 10 = assignment.
// ---------------------------------------------------------------------------
__global__ __launch_bounds__(THR)
void mainKernel(const float* __restrict__ outputs,
                const float* __restrict__ targets,
                float* __restrict__ out) {
    const int b    = blockIdx.x;
    const int part = blockIdx.y;
    const int tid  = threadIdx.x;

    __shared__ float4 s_gt[TT];      // scaled (X1,Y1,X2,Y2), sanitized
    __shared__ float  s_mg4[TT];     // -12 * unscaled gt area (flag constant)
    __shared__ float  s_ga7[TT];     // 7 * unscaled gt area (assignment)
    // compacted gt list (streaming), +2 sentinel slots
    __shared__ float4 s_cgt[TT+2];   // (X2, Y2, -X1, -Y1)
    __shared__ float  s_cmg[TT+2];   // -12*ga
    __shared__ int    s_cnt;
    __shared__ float4 s_bbox;
    __shared__ float  s_wlo[NW][2], s_whi[NW][2];
    // assignment-only
    __shared__ int    s_slot[TT];
    __shared__ int    s_valid[TT];
    __shared__ float4 s_tb[TT];
    __shared__ int    s_cls[TT];

    if (tid == 0) s_cnt = 0;

    // ---- gt decode ----
    if (tid < TT) {
        const float* g = targets + ((size_t)b * TT + tid) * 5;
        float x1 = g[0], y1 = g[1], x2 = g[2], y2 = g[3], cl = g[4];
        bool valid = (x1 + y1 + x2 + y2) > 0.0f;

        float gx1 = x1 * FWW, gy1 = y1 * FHH, gx2 = x2 * FWW, gy2 = y2 * FHH;
        float gw = gx2 - gx1, gh = gy2 - gy1;
        float ga = gw * gh;

        if (valid) {
            s_gt[tid] = make_float4(SQ7*gx1, SQ7*gy1, SQ7*gx2, SQ7*gy2);
            s_mg4[tid] = 4.0f * (-3.0f * ga);
            s_ga7[tid] = 7.0f * ga;
        } else {
            s_gt[tid] = make_float4(1e8f, 1e8f, 1e8f, 1e8f);
            s_mg4[tid] = 0.0f;
            s_ga7[tid] = 0.0f;
        }

        if (part == SPARTS) {
            float gcx = 0.5f * (gx1 + gx2), gcy = 0.5f * (gy1 + gy2);
            int cx = min(max((int)floorf(gcx), 0), FWW - 1);
            int cy = min(max((int)floorf(gcy), 0), FHH - 1);
            int cell = cy * FWW + cx;

            float acx = (float)cx + 0.5f, acy = (float)cy + 0.5f;
            float best = -1e30f;
            int aidx = 0;
            #pragma unroll
            for (int a = 0; a < AA; a++) {
                float aw = c_aw[a], ah = c_ah[a];
                float ax1 = acx - 0.5f*aw, ax2 = acx + 0.5f*aw;
                float ay1 = acy - 0.5f*ah, ay2 = acy + 0.5f*ah;
                float xi1 = fmaxf(ax1, gx1), yi1 = fmaxf(ay1, gy1);
                float xi2 = fminf(ax2, gx2), yi2 = fminf(ay2, gy2);
                float inter = fmaxf(xi2 - xi1, 0.0f) * fmaxf(yi2 - yi1, 0.0f);
                float iou = inter / (aw * ah + ga - inter);
                if (iou > best) { best = iou; aidx = a; }
            }
            s_tb[tid]   = make_float4(gcx - (float)cx, gcy - (float)cy,
                                      gw / c_aw[aidx], gh / c_ah[aidx]);
            s_cls[tid]  = (int)cl;
            s_slot[tid] = cell * AA + aidx;
            s_valid[tid] = valid ? 1 : 0;
        }
    }

    const float* ob = outputs + (size_t)b * CH * KA;

    float r0 = 0.0f, r1 = 0.0f, r2 = 0.0f, r3 = 0.0f;

    if (part < SPARTS) {
        // -------------------- streaming: anchor a, y-half tile --------------
        const int a    = part >> 1;
        const int tile = part & 1;
        const int kbase = tile * CPT;          // contiguous 338-cell range
        const float* pbase = ob + (size_t)(a * CH) * KK;

        float nx1[NA], ny1[NA], px2[NA], py2[NA], pa12[NA], c2[NA];
        bool v[NA];
        #pragma unroll
        for (int j = 0; j < NA; j++) {
            int slot = tid + j * THR;
            v[j] = slot < CPT;
            int k = kbase + (v[j] ? slot : (CPT - 1));
            int yy = k / FWW, xx = k - yy * FWW;
            float conf, sx, sy, ew, eh, pa7, pa3;
            decode_core(pbase + k, a, xx, yy, nx1[j], ny1[j], px2[j], py2[j],
                        pa3, conf, sx, sy, ew, eh, pa7);
            pa12[j] = 4.0f * pa3;
            c2[j] = conf * conf;
        }

        // block bbox (padded anchors only enlarge -> safe)
        float bxlo = -nx1[0], bylo = -ny1[0], bxhi = px2[0], byhi = py2[0];
        #pragma unroll
        for (int j = 1; j < NA; j++) {
            bxlo = fminf(bxlo, -nx1[j]); bylo = fminf(bylo, -ny1[j]);
            bxhi = fmaxf(bxhi, px2[j]);  byhi = fmaxf(byhi, py2[j]);
        }
        #pragma unroll
        for (int o = 16; o > 0; o >>= 1) {
            bxlo = fminf(bxlo, __shfl_xor_sync(0xffffffffu, bxlo, o));
            bylo = fminf(bylo, __shfl_xor_sync(0xffffffffu, bylo, o));
            bxhi = fmaxf(bxhi, __shfl_xor_sync(0xffffffffu, bxhi, o));
            byhi = fmaxf(byhi, __shfl_xor_sync(0xffffffffu, byhi, o));
        }
        int w = tid >> 5;
        if ((tid & 31) == 0) {
            s_wlo[w][0] = bxlo; s_wlo[w][1] = bylo;
            s_whi[w][0] = bxhi; s_whi[w][1] = byhi;
        }
        __syncthreads();
        if (tid == 0) {
            float xl = s_wlo[0][0], yl = s_wlo[0][1];
            float xh = s_whi[0][0], yh = s_whi[0][1];
            #pragma unroll
            for (int i = 1; i < NW; i++) {
                xl = fminf(xl, s_wlo[i][0]); yl = fminf(yl, s_wlo[i][1]);
                xh = fmaxf(xh, s_whi[i][0]); yh = fmaxf(yh, s_whi[i][1]);
            }
            s_bbox = make_float4(xl, yl, xh, yh);
        }
        __syncthreads();

        // compact gts overlapping block bbox (order irrelevant: exact max/flags)
        if (tid < TT) {
            float4 g = s_gt[tid];
            float4 bbx = s_bbox;
            if (g.x < bbx.z && g.z > bbx.x && g.y < bbx.w && g.w > bbx.y) {
                int i = atomicAdd(&s_cnt, 1);
                s_cgt[i] = make_float4(g.z, g.w, -g.x, -g.y);
                s_cmg[i] = s_mg4[tid];
            }
        }
        __syncthreads();
        // sentinels (exact no-ops: u=v=0, mg=0 -> f=0 <= acc)
        if (tid < 2) {
            s_cgt[s_cnt + tid] = make_float4(-1e8f, -1e8f, -1e8f, -1e8f);
            s_cmg[s_cnt + tid] = 0.0f;
        }
        __syncthreads();

        const int cntUp = (s_cnt + 1) & ~1;
        float acc4[NA];
        #pragma unroll
        for (int j = 0; j < NA; j++) acc4[j] = 0.0f;

        for (int i = 0; i < cntUp; i += 2) {
            float4 cA = s_cgt[i],   cB = s_cgt[i+1];
            float mgA = s_cmg[i],   mgB = s_cmg[i+1];
            #pragma unroll
            for (int j = 0; j < NA; j++) {
                // pipe-balanced: 4 min + 1 max (alu), 4 add + 1 fma (fma)
                float dxA = fminf(px2[j], cA.x) + fminf(nx1[j], cA.z);
                float dyA = fminf(py2[j], cA.y) + fminf(ny1[j], cA.w);
                float uA = dxA + fabsf(dxA);   // = 2*max(dxA,0) exactly
                float vA = dyA + fabsf(dyA);
                acc4[j] = fmaxf(acc4[j], fmaf(uA, vA, mgA));
            }
            #pragma unroll
            for (int j = 0; j < NA; j++) {
                float dxB = fminf(px2[j], cB.x) + fminf(nx1[j], cB.z);
                float dyB = fminf(py2[j], cB.y) + fminf(ny1[j], cB.w);
                float uB = dxB + fabsf(dxB);
                float vB = dyB + fabsf(dyB);
                acc4[j] = fmaxf(acc4[j], fmaf(uB, vB, mgB));
            }
        }

        float posAny = 0.0f;
        #pragma unroll
        for (int j = 0; j < NA; j++) {
            if (v[j]) {
                r0 += c2[j];
                if (acc4[j] >= pa12[j]) r1 += c2[j];
                if (acc4[j] >  pa12[j]) posAny = 1.0f;
            }
        }
        r3 = posAny;
    } else {
        // -------------------- assignment part -------------------------------
        __syncthreads();
        __shared__ int s_fslot[TT];
        if (tid < TT) {
            int slot = s_slot[tid];
            bool fin = (s_valid[tid] != 0);
            if (fin) {
                for (int t2 = tid + 1; t2 < TT; t2++)
                    if (s_valid[t2] && s_slot[t2] == slot) { fin = false; break; }
            }
            s_fslot[tid] = fin ? slot : -1;
        }
        __syncthreads();

        if (tid < TT && s_fslot[tid] >= 0) {
            int slot = s_fslot[tid];
            int k = slot / AA, a = slot - k * AA;
            int yy = k / FWW, xx = k - yy * FWW;
            const float* p = ob + (size_t)(a * CH) * KK + k;

            float nx1, ny1, px2, py2, pa3, conf, sx, sy, ew, eh, pa7;
            decode_core(p, a, xx, yy, nx1, ny1, px2, py2, pa3,
                        conf, sx, sy, ew, eh, pa7);
            float pa12 = 4.0f * pa3;

            // exact max-IoU over ALL gts + SAME flag expression as streaming
            float bi = 0.0f, bd = 1.0f, acc4 = 0.0f;
            for (int t = 0; t < TT; t++) {
                float4 g = s_gt[t];
                float dx = fminf(px2, g.z) + fminf(nx1, -g.x);
                float dy = fminf(py2, g.w) + fminf(ny1, -g.y);
                float u = dx + fabsf(dx);
                float vv = dy + fabsf(dy);
                acc4 = fmaxf(acc4, fmaf(u, vv, s_mg4[t]));
                float ix = 0.5f * u;                 // = max(dx,0) exactly
                float iy = 0.5f * vv;
                float inter = ix * iy;               // scaled (=7*inter)
                float den = pa7 + s_ga7[t] - inter;
                bool win = (inter * bd > bi * den);
                bi = win ? inter : bi;
                bd = win ? den : bd;
            }
            float miou = bi / bd;

            float4 tb = s_tb[tid];
            float d0 = sx - tb.x, d1 = sy - tb.y;
            float d2 = ew - tb.z, d3 = eh - tb.w;
            float asg = 0.5f * (d0*d0 + d1*d1 + d2*d2 + d3*d3);
            float di = OBJ_SCALE * conf - OBJ_SCALE * miou;
            asg += 0.5f * di * di;
            float lmax = -1e30f;
            #pragma unroll
            for (int c = 0; c < NCLS; c++) lmax = fmaxf(lmax, p[(5 + c) * KK]);
            float se = 0.0f;
            #pragma unroll
            for (int c = 0; c < NCLS; c++) se += __expf(p[(5 + c) * KK] - lmax);
            asg += (lmax + __logf(se)) - p[(5 + s_cls[tid]) * KK];

            r2 = asg;
            float cc = conf * conf;
            r0 = -cc;
            if (acc4 >= pa12) r1 = -cc;
        }
    }

    // ---- block reduction ----
    #pragma unroll
    for (int o = 16; o > 0; o >>= 1) {
        r0 += __shfl_down_sync(0xffffffffu, r0, o);
        r1 += __shfl_down_sync(0xffffffffu, r1, o);
        r2 += __shfl_down_sync(0xffffffffu, r2, o);
        r3 += __shfl_down_sync(0xffffffffu, r3, o);
    }
    __shared__ float rA[NW], rBs[NW], rG[NW], rP[NW];
    int w2 = tid >> 5, l2 = tid & 31;
    if (l2 == 0) { rA[w2] = r0; rBs[w2] = r1; rG[w2] = r2; rP[w2] = r3; }
    __syncthreads();

    __shared__ int s_last;
    if (tid == 0) {
        float a0 = 0, b0 = 0, g0 = 0, p0 = 0;
        #pragma unroll
        for (int i = 0; i < NW; i++) {
            a0 += rA[i]; b0 += rBs[i]; g0 += rG[i]; p0 += rP[i];
        }
        g_part[b][part] = make_float4(a0, b0, g0, p0);
        __threadfence();
        unsigned done = atomicAdd(&g_done, 1u);
        s_last = (done == (unsigned)(BB * NPARTS - 1)) ? 1 : 0;
    }
    __syncthreads();

    // ---- last block: global combine (deterministic order) ----
    if (s_last) {
        __shared__ float red[64];
        if (tid < 64) {
            float accl = 0.0f;
            for (int bb = tid; bb < BB; bb += 64) {
                float sA = 0, sB = 0, sG = 0, sP = 0;
                #pragma unroll
                for (int p = 0; p < NPARTS; p++) {
                    float4 vv = g_part[bb][p];
                    sA += vv.x; sB += vv.y; sG += vv.z; sP += vv.w;
                }
                bool pos = sP > 0.0f;
                accl += 0.5f * (sA - (pos ? sB : 0.0f)) + sG;
            }
            red[tid] = accl;
        }
        __syncthreads();
        #pragma unroll
        for (int s = 32; s > 0; s >>= 1) {
            if (tid < s) red[tid] += red[tid + s];
            __syncthreads();
        }
        if (tid == 0) {
            out[0] = red[0] / (float)BB;
            g_done = 0;  // reset for next graph replay
        }
    }
}

// ---------------------------------------------------------------------------
extern "C" void kernel_launch(void* const* d_in, const int* in_sizes, int n_in,
                              void* d_out, int out_size) {
    const float* outputs = (const float*)d_in[0];
    const float* targets = (const float*)d_in[1];
    if (n_in >= 2 && in_sizes[0] < in_sizes[1]) {
        outputs = (const float*)d_in[1];
        targets = (const float*)d_in[0];
    }
    float* out = (float*)d_out;

    dim3 grid(BB, NPARTS);
    mainKernel<<<grid, THR>>>(outputs, targets, out);
}

// round 7
// speedup vs baseline: 1.5028x; 1.2448x over previous
#include <cuda_runtime.h>
#include <cuda_bf16.h>

// Problem constants
#define BB 128
#define FHH 26
#define FWW 26
#define TT 50
#define AA 5
#define NCLS 20
#define KK (FHH*FWW)          // 676
#define KA (KK*AA)            // 3380
#define CH (5+NCLS)           // 25
#define OBJ_SCALE 5.0f

#define TILES 2               // split grid into 2 y-halves (13 rows each)
#define CPT (KK/TILES)        // 338 cells per tile (contiguous k range)
#define SPARTS (AA*TILES)     // 10 streaming parts
#define NPARTS (SPARTS + 1)   // + assignment part
#define THR 96
#define NA 4                  // cells per thread (96*4 = 384 >= 338)
#define NW (THR/32)           // 3 warps
#define SQ7 2.6457513110645906f

__constant__ float c_aw[AA] = {1.3221f, 3.19275f, 5.05587f, 9.47112f, 11.2364f};
__constant__ float c_ah[AA] = {1.73145f, 4.00944f, 8.09892f, 4.84053f, 10.0071f};

// Scratch
__device__ float4 g_part[BB][NPARTS];
__device__ unsigned g_done = 0;

__device__ __forceinline__ float sigmoidf_(float x) {
    return 1.0f / (1.0f + __expf(-x));
}

// Decode (sqrt7-scaled corners; nx1/ny1 = NEGATED lower corners).
__device__ __forceinline__ void decode_core(
    const float* __restrict__ p, int a, int xx, int yy,
    float& nx1, float& ny1, float& px2, float& py2,
    float& pa3, float& conf, float& sx, float& sy,
    float& ew, float& eh, float& pa7)
{
    float tx = p[0], ty = p[KK], tw = p[2*KK], th = p[3*KK], tc = p[4*KK];
    sx = sigmoidf_(tx); sy = sigmoidf_(ty);
    ew = __expf(tw);    eh = __expf(th);
    conf = sigmoidf_(tc);
    float pw = c_aw[a] * ew, ph = c_ah[a] * eh;
    float pa = pw * ph;
    pa3 = 3.0f * pa;
    float pcx = (float)xx + sx, pcy = (float)yy + sy;
    float pwS = SQ7 * pw, phS = SQ7 * ph;
    float px1 = fmaf(SQ7, pcx, -0.5f * pwS);
    px2       = fmaf(SQ7, pcx,  0.5f * pwS);
    float py1 = fmaf(SQ7, pcy, -0.5f * phS);
    py2       = fmaf(SQ7, pcy,  0.5f * phS);
    nx1 = -px1; ny1 = -py1;
    pa7 = pwS * phS;
}

// ---------------------------------------------------------------------------
// grid (B, 11): part = a*2 + tile for part < 10; part 10 = assignment.
// ---------------------------------------------------------------------------
__global__ __launch_bounds__(THR)
void mainKernel(const float* __restrict__ outputs,
                const float* __restrict__ targets,
                float* __restrict__ out) {
    const int b    = blockIdx.x;
    const int part = blockIdx.y;
    const int tid  = threadIdx.x;

    __shared__ float4 s_gt[TT];      // scaled (X1,Y1,X2,Y2), sanitized
    __shared__ float  s_mg4[TT];     // -12 * unscaled gt area (flag constant)
    __shared__ float  s_ga7[TT];     // 7 * unscaled gt area (assignment)
    // compacted gt list (streaming), +2 sentinel slots
    __shared__ float4 s_cgt[TT+2];   // (X2, Y2, -X1, -Y1)
    __shared__ float  s_cmg[TT+2];   // -12*ga
    __shared__ int    s_cnt;
    __shared__ float4 s_bbox;
    __shared__ float2 s_parange;     // (pa12_min, pa12_max) over block anchors
    __shared__ float  s_wlo[NW][3], s_whi[NW][3];
    // assignment-only
    __shared__ int    s_slot[TT];
    __shared__ int    s_valid[TT];
    __shared__ float4 s_tb[TT];
    __shared__ int    s_cls[TT];

    if (tid == 0) s_cnt = 0;

    // ---- gt decode ----
    if (tid < TT) {
        const float* g = targets + ((size_t)b * TT + tid) * 5;
        float x1 = g[0], y1 = g[1], x2 = g[2], y2 = g[3], cl = g[4];
        bool valid = (x1 + y1 + x2 + y2) > 0.0f;

        float gx1 = x1 * FWW, gy1 = y1 * FHH, gx2 = x2 * FWW, gy2 = y2 * FHH;
        float gw = gx2 - gx1, gh = gy2 - gy1;
        float ga = gw * gh;

        if (valid) {
            s_gt[tid] = make_float4(SQ7*gx1, SQ7*gy1, SQ7*gx2, SQ7*gy2);
            s_mg4[tid] = 4.0f * (-3.0f * ga);
            s_ga7[tid] = 7.0f * ga;
        } else {
            s_gt[tid] = make_float4(1e8f, 1e8f, 1e8f, 1e8f);
            s_mg4[tid] = 0.0f;
            s_ga7[tid] = 0.0f;
        }

        if (part == SPARTS) {
            float gcx = 0.5f * (gx1 + gx2), gcy = 0.5f * (gy1 + gy2);
            int cx = min(max((int)floorf(gcx), 0), FWW - 1);
            int cy = min(max((int)floorf(gcy), 0), FHH - 1);
            int cell = cy * FWW + cx;

            float acx = (float)cx + 0.5f, acy = (float)cy + 0.5f;
            float best = -1e30f;
            int aidx = 0;
            #pragma unroll
            for (int a = 0; a < AA; a++) {
                float aw = c_aw[a], ah = c_ah[a];
                float ax1 = acx - 0.5f*aw, ax2 = acx + 0.5f*aw;
                float ay1 = acy - 0.5f*ah, ay2 = acy + 0.5f*ah;
                float xi1 = fmaxf(ax1, gx1), yi1 = fmaxf(ay1, gy1);
                float xi2 = fminf(ax2, gx2), yi2 = fminf(ay2, gy2);
                float inter = fmaxf(xi2 - xi1, 0.0f) * fmaxf(yi2 - yi1, 0.0f);
                float iou = inter / (aw * ah + ga - inter);
                if (iou > best) { best = iou; aidx = a; }
            }
            s_tb[tid]   = make_float4(gcx - (float)cx, gcy - (float)cy,
                                      gw / c_aw[aidx], gh / c_ah[aidx]);
            s_cls[tid]  = (int)cl;
            s_slot[tid] = cell * AA + aidx;
            s_valid[tid] = valid ? 1 : 0;
        }
    }

    const float* ob = outputs + (size_t)b * CH * KA;

    float r0 = 0.0f, r1 = 0.0f, r2 = 0.0f, r3 = 0.0f;

    if (part < SPARTS) {
        // -------------------- streaming: anchor a, y-half tile --------------
        const int a    = part >> 1;
        const int tile = part & 1;
        const int kbase = tile * CPT;          // contiguous 338-cell range
        const float* pbase = ob + (size_t)(a * CH) * KK;

        float nx1[NA], ny1[NA], px2[NA], py2[NA], pa12[NA], c2[NA];
        bool v[NA];
        #pragma unroll
        for (int j = 0; j < NA; j++) {
            int slot = tid + j * THR;
            v[j] = slot < CPT;
            int k = kbase + (v[j] ? slot : (CPT - 1));
            int yy = k / FWW, xx = k - yy * FWW;
            float conf, sx, sy, ew, eh, pa7, pa3;
            decode_core(pbase + k, a, xx, yy, nx1[j], ny1[j], px2[j], py2[j],
                        pa3, conf, sx, sy, ew, eh, pa7);
            pa12[j] = 4.0f * pa3;
            c2[j] = conf * conf;
        }

        // block bbox + pa12 range (padded anchors duplicate a real cell -> exact)
        float bxlo = -nx1[0], bylo = -ny1[0], bxhi = px2[0], byhi = py2[0];
        float pmn = pa12[0], pmx = pa12[0];
        #pragma unroll
        for (int j = 1; j < NA; j++) {
            bxlo = fminf(bxlo, -nx1[j]); bylo = fminf(bylo, -ny1[j]);
            bxhi = fmaxf(bxhi, px2[j]);  byhi = fmaxf(byhi, py2[j]);
            pmn = fminf(pmn, pa12[j]);   pmx = fmaxf(pmx, pa12[j]);
        }
        #pragma unroll
        for (int o = 16; o > 0; o >>= 1) {
            bxlo = fminf(bxlo, __shfl_xor_sync(0xffffffffu, bxlo, o));
            bylo = fminf(bylo, __shfl_xor_sync(0xffffffffu, bylo, o));
            bxhi = fmaxf(bxhi, __shfl_xor_sync(0xffffffffu, bxhi, o));
            byhi = fmaxf(byhi, __shfl_xor_sync(0xffffffffu, byhi, o));
            pmn  = fminf(pmn,  __shfl_xor_sync(0xffffffffu, pmn,  o));
            pmx  = fmaxf(pmx,  __shfl_xor_sync(0xffffffffu, pmx,  o));
        }
        int w = tid >> 5;
        if ((tid & 31) == 0) {
            s_wlo[w][0] = bxlo; s_wlo[w][1] = bylo; s_wlo[w][2] = pmn;
            s_whi[w][0] = bxhi; s_whi[w][1] = byhi; s_whi[w][2] = pmx;
        }
        __syncthreads();
        if (tid == 0) {
            float xl = s_wlo[0][0], yl = s_wlo[0][1], pn = s_wlo[0][2];
            float xh = s_whi[0][0], yh = s_whi[0][1], px = s_whi[0][2];
            #pragma unroll
            for (int i = 1; i < NW; i++) {
                xl = fminf(xl, s_wlo[i][0]); yl = fminf(yl, s_wlo[i][1]);
                pn = fminf(pn, s_wlo[i][2]);
                xh = fmaxf(xh, s_whi[i][0]); yh = fmaxf(yh, s_whi[i][1]);
                px = fmaxf(px, s_whi[i][2]);
            }
            s_bbox = make_float4(xl, yl, xh, yh);
            s_parange = make_float2(pn, px);
        }
        __syncthreads();

        // compact gts: bbox overlap AND area-ratio feasibility.
        // IoU >= 0.75 requires ga in [0.75*pa, 4/3*pa]; with 12ga = -mg4 and
        // pa12 = 12pa, keep iff 12ga >= 0.749*pa12_min && 12ga <= 1.335*pa12_max.
        // (slack 1e-3 >> 1e-6 rounding; culled gts provably can't reach the
        //  threshold, so max-based flags are unchanged -> exact.)
        if (tid < TT) {
            float4 g = s_gt[tid];
            float4 bbx = s_bbox;
            float2 pr = s_parange;
            float ga12 = -s_mg4[tid];
            if (g.x < bbx.z && g.z > bbx.x && g.y < bbx.w && g.w > bbx.y &&
                ga12 >= 0.749f * pr.x && ga12 <= 1.335f * pr.y) {
                int i = atomicAdd(&s_cnt, 1);
                s_cgt[i] = make_float4(g.z, g.w, -g.x, -g.y);
                s_cmg[i] = s_mg4[tid];
            }
        }
        __syncthreads();
        // sentinels (exact no-ops: u=v=0, mg=0 -> f=0 <= acc)
        if (tid < 2) {
            s_cgt[s_cnt + tid] = make_float4(-1e8f, -1e8f, -1e8f, -1e8f);
            s_cmg[s_cnt + tid] = 0.0f;
        }
        __syncthreads();

        const int cntUp = (s_cnt + 1) & ~1;
        float acc4[NA];
        #pragma unroll
        for (int j = 0; j < NA; j++) acc4[j] = 0.0f;

        for (int i = 0; i < cntUp; i += 2) {
            float4 cA = s_cgt[i],   cB = s_cgt[i+1];
            float mgA = s_cmg[i],   mgB = s_cmg[i+1];
            #pragma unroll
            for (int j = 0; j < NA; j++) {
                float dxA = fminf(px2[j], cA.x) + fminf(nx1[j], cA.z);
                float dyA = fminf(py2[j], cA.y) + fminf(ny1[j], cA.w);
                float uA = dxA + fabsf(dxA);   // = 2*max(dxA,0) exactly
                float vA = dyA + fabsf(dyA);
                acc4[j] = fmaxf(acc4[j], fmaf(uA, vA, mgA));
            }
            #pragma unroll
            for (int j = 0; j < NA; j++) {
                float dxB = fminf(px2[j], cB.x) + fminf(nx1[j], cB.z);
                float dyB = fminf(py2[j], cB.y) + fminf(ny1[j], cB.w);
                float uB = dxB + fabsf(dxB);
                float vB = dyB + fabsf(dyB);
                acc4[j] = fmaxf(acc4[j], fmaf(uB, vB, mgB));
            }
        }

        float posAny = 0.0f;
        #pragma unroll
        for (int j = 0; j < NA; j++) {
            if (v[j]) {
                r0 += c2[j];
                if (acc4[j] >= pa12[j]) r1 += c2[j];
                if (acc4[j] >  pa12[j]) posAny = 1.0f;
            }
        }
        r3 = posAny;
    } else {
        // -------------------- assignment part -------------------------------
        __syncthreads();
        __shared__ int s_fslot[TT];
        if (tid < TT) {
            int slot = s_slot[tid];
            bool fin = (s_valid[tid] != 0);
            if (fin) {
                for (int t2 = tid + 1; t2 < TT; t2++)
                    if (s_valid[t2] && s_slot[t2] == slot) { fin = false; break; }
            }
            s_fslot[tid] = fin ? slot : -1;
        }
        __syncthreads();

        if (tid < TT && s_fslot[tid] >= 0) {
            int slot = s_fslot[tid];
            int k = slot / AA, a = slot - k * AA;
            int yy = k / FWW, xx = k - yy * FWW;
            const float* p = ob + (size_t)(a * CH) * KK + k;

            float nx1, ny1, px2, py2, pa3, conf, sx, sy, ew, eh, pa7;
            decode_core(p, a, xx, yy, nx1, ny1, px2, py2, pa3,
                        conf, sx, sy, ew, eh, pa7);
            float pa12 = 4.0f * pa3;

            // exact max-IoU over ALL gts + SAME flag expression as streaming
            float bi = 0.0f, bd = 1.0f, acc4 = 0.0f;
            for (int t = 0; t < TT; t++) {
                float4 g = s_gt[t];
                float dx = fminf(px2, g.z) + fminf(nx1, -g.x);
                float dy = fminf(py2, g.w) + fminf(ny1, -g.y);
                float u = dx + fabsf(dx);
                float vv = dy + fabsf(dy);
                acc4 = fmaxf(acc4, fmaf(u, vv, s_mg4[t]));
                float ix = 0.5f * u;                 // = max(dx,0) exactly
                float iy = 0.5f * vv;
                float inter = ix * iy;               // scaled (=7*inter)
                float den = pa7 + s_ga7[t] - inter;
                bool win = (inter * bd > bi * den);
                bi = win ? inter : bi;
                bd = win ? den : bd;
            }
            float miou = bi / bd;

            float4 tb = s_tb[tid];
            float d0 = sx - tb.x, d1 = sy - tb.y;
            float d2 = ew - tb.z, d3 = eh - tb.w;
            float asg = 0.5f * (d0*d0 + d1*d1 + d2*d2 + d3*d3);
            float di = OBJ_SCALE * conf - OBJ_SCALE * miou;
            asg += 0.5f * di * di;
            float lmax = -1e30f;
            #pragma unroll
            for (int c = 0; c < NCLS; c++) lmax = fmaxf(lmax, p[(5 + c) * KK]);
            float se = 0.0f;
            #pragma unroll
            for (int c = 0; c < NCLS; c++) se += __expf(p[(5 + c) * KK] - lmax);
            asg += (lmax + __logf(se)) - p[(5 + s_cls[tid]) * KK];

            r2 = asg;
            float cc = conf * conf;
            r0 = -cc;
            if (acc4 >= pa12) r1 = -cc;
        }
    }

    // ---- block reduction ----
    #pragma unroll
    for (int o = 16; o > 0; o >>= 1) {
        r0 += __shfl_down_sync(0xffffffffu, r0, o);
        r1 += __shfl_down_sync(0xffffffffu, r1, o);
        r2 += __shfl_down_sync(0xffffffffu, r2, o);
        r3 += __shfl_down_sync(0xffffffffu, r3, o);
    }
    __shared__ float rA[NW], rBs[NW], rG[NW], rP[NW];
    int w2 = tid >> 5, l2 = tid & 31;
    if (l2 == 0) { rA[w2] = r0; rBs[w2] = r1; rG[w2] = r2; rP[w2] = r3; }
    __syncthreads();

    __shared__ int s_last;
    if (tid == 0) {
        float a0 = 0, b0 = 0, g0 = 0, p0 = 0;
        #pragma unroll
        for (int i = 0; i < NW; i++) {
            a0 += rA[i]; b0 += rBs[i]; g0 += rG[i]; p0 += rP[i];
        }
        g_part[b][part] = make_float4(a0, b0, g0, p0);
        __threadfence();
        unsigned done = atomicAdd(&g_done, 1u);
        s_last = (done == (unsigned)(BB * NPARTS - 1)) ? 1 : 0;
    }
    __syncthreads();

    // ---- last block: global combine (deterministic order) ----
    if (s_last) {
        __shared__ float red[64];
        if (tid < 64) {
            float accl = 0.0f;
            for (int bb = tid; bb < BB; bb += 64) {
                float sA = 0, sB = 0, sG = 0, sP = 0;
                #pragma unroll
                for (int p = 0; p < NPARTS; p++) {
                    float4 vv = g_part[bb][p];
                    sA += vv.x; sB += vv.y; sG += vv.z; sP += vv.w;
                }
                bool pos = sP > 0.0f;
                accl += 0.5f * (sA - (pos ? sB : 0.0f)) + sG;
            }
            red[tid] = accl;
        }
        __syncthreads();
        #pragma unroll
        for (int s = 32; s > 0; s >>= 1) {
            if (tid < s) red[tid] += red[tid + s];
            __syncthreads();
        }
        if (tid == 0) {
            out[0] = red[0] / (float)BB;
            g_done = 0;  // reset for next graph replay
        }
    }
}

// ---------------------------------------------------------------------------
extern "C" void kernel_launch(void* const* d_in, const int* in_sizes, int n_in,
                              void* d_out, int out_size) {
    const float* outputs = (const float*)d_in[0];
    const float* targets = (const float*)d_in[1];
    if (n_in >= 2 && in_sizes[0] < in_sizes[1]) {
        outputs = (const float*)d_in[1];
        targets = (const float*)d_in[0];
    }
    float* out = (float*)d_out;

    dim3 grid(BB, NPARTS);
    mainKernel<<<grid, THR>>>(outputs, targets, out);
}